// round 10
// baseline (speedup 1.0000x reference)
#include <cuda_runtime.h>
#include <cuda_fp16.h>

#define NB 8       // batch
#define NT 12      // time / feature-in dim
#define NN 20000   // nodes
#define NE 320000  // edges
#define NF 64      // gcn hidden
#define NBT (NB * NT)   // 96 values per node row
#define CAP 64          // bucket capacity (Poisson(16); P(>64) ~ 1e-20)

#define TP_BLOCKS (NN / 32)        // 625 transpose blocks (32 nodes each)
#define FILL_BLOCKS (NE / 256)     // 1250 fill blocks (exact)

// Scratch (__device__ globals; ~21 MB, L2-resident).
// g_cnt starts zeroed (static init) and is re-zeroed by k2 every call.
__device__ __align__(128) uint2 g_xth[(size_t)NN * 24];   // fp16 xt: [n][96 halves]
__device__ __align__(128) float g_agg[(size_t)NN * NBT];  // fp32 [n][b*12+t]
__device__ __align__(128) int2  g_bkt[(size_t)NN * CAP];  // {src, w-as-int}
__device__ int g_cnt[NN];

// ---- f32x2 packed helpers ---------------------------------------------------
__device__ __forceinline__ unsigned long long pk2(float lo, float hi) {
    unsigned long long r;
    asm("mov.b64 %0, {%1, %2};" : "=l"(r) : "f"(lo), "f"(hi));
    return r;
}
__device__ __forceinline__ void upk2(float& lo, float& hi, unsigned long long v) {
    asm("mov.b64 {%0, %1}, %2;" : "=f"(lo), "=f"(hi) : "l"(v));
}
#define FFMA2(d, a, b, c) \
    asm("fma.rn.f32x2 %0, %1, %2, %3;" : "=l"(d) : "l"(a), "l"(b), "l"(c))

__device__ __forceinline__ uint2 pack4h(float a, float b, float c, float d) {
    __half2 lo = __floats2half2_rn(a, b);
    __half2 hi = __floats2half2_rn(c, d);
    uint2 r;
    r.x = *reinterpret_cast<unsigned*>(&lo);
    r.y = *reinterpret_cast<unsigned*>(&hi);
    return r;
}

// ---------------------------------------------------------------------------
// kA: fused transpose(+fp16 convert) + edge bucketing.
// ---------------------------------------------------------------------------
__global__ void __launch_bounds__(256) kA(
        const float* __restrict__ x,
        const int* __restrict__ esrc, const int* __restrict__ edst,
        const float* __restrict__ ew) {
    __shared__ float s[96 * 33];
    int tid = threadIdx.x;

    if (blockIdx.x < TP_BLOCKS) {
        int n0 = blockIdx.x * 32;
        const float4* x4 = reinterpret_cast<const float4*>(x);
#pragma unroll
        for (int k = 0; k < 3; ++k) {
            int i = tid + 256 * k;
            int bt = i >> 3, q = i & 7;
            float4 v = x4[(size_t)bt * (NN / 4) + (n0 >> 2) + q];
            s[bt * 33 + 4 * q + 0] = v.x;
            s[bt * 33 + 4 * q + 1] = v.y;
            s[bt * 33 + 4 * q + 2] = v.z;
            s[bt * 33 + 4 * q + 3] = v.w;
        }
        __syncthreads();
        uint2* dst = g_xth + (size_t)n0 * 24;
#pragma unroll
        for (int k = 0; k < 3; ++k) {
            int o2 = tid + 256 * k;         // 0..767 contiguous 8B stores
            int n = o2 / 24, q = o2 % 24, r = 4 * q;
            dst[o2] = pack4h(s[(r + 0) * 33 + n], s[(r + 1) * 33 + n],
                             s[(r + 2) * 33 + n], s[(r + 3) * 33 + n]);
        }
    } else {
        int e = (blockIdx.x - TP_BLOCKS) * 256 + tid;
        int d = edst[e];
        int pos = atomicAdd(&g_cnt[d], 1);
        if (pos < CAP)
            g_bkt[(size_t)d * CAP + pos] = make_int2(esrc[e], __float_as_int(ew[e]));
    }
}

// ---------------------------------------------------------------------------
// k2: pure gather, one warp per node. Per edge: 1 LDG.64 of 4 fp16 (lane<24),
// cvt to fp32, 4 FFMA. Rows are 192B = 2 L2 lines (was 384B/3 lines).
// fp32 accumulate; writes fp32 agg row (coalesced float4). Resets g_cnt.
// ---------------------------------------------------------------------------
__global__ void __launch_bounds__(256) k2_gather(
        const int* __restrict__ esrc, const int* __restrict__ edst,
        const float* __restrict__ ew) {
    int tid = threadIdx.x;
    int w = tid >> 5, lane = tid & 31;
    int node = blockIdx.x * 8 + w;
    int cnt = g_cnt[node];
    if (lane == 0) g_cnt[node] = 0;

    float4 acc = make_float4(0.f, 0.f, 0.f, 0.f);

    if (cnt <= CAP) {
        const int2* bp = g_bkt + (size_t)node * CAP;
        int2 sl0 = (lane      < cnt) ? bp[lane]      : make_int2(0, 0);
        int2 sl1 = (lane + 32 < cnt) ? bp[lane + 32] : make_int2(0, 0);

        int c1 = cnt < 32 ? cnt : 32;
        for (int j = 0; j < c1; j += 4) {   // padded slots carry w=0
            int   s0 = __shfl_sync(~0u, sl0.x, j + 0);
            int   s1 = __shfl_sync(~0u, sl0.x, j + 1);
            int   s2 = __shfl_sync(~0u, sl0.x, j + 2);
            int   s3 = __shfl_sync(~0u, sl0.x, j + 3);
            float w0 = __int_as_float(__shfl_sync(~0u, sl0.y, j + 0));
            float w1 = __int_as_float(__shfl_sync(~0u, sl0.y, j + 1));
            float w2 = __int_as_float(__shfl_sync(~0u, sl0.y, j + 2));
            float w3 = __int_as_float(__shfl_sync(~0u, sl0.y, j + 3));
            if (lane < 24) {
                uint2 u0 = g_xth[(size_t)s0 * 24 + lane];
                uint2 u1 = g_xth[(size_t)s1 * 24 + lane];
                uint2 u2 = g_xth[(size_t)s2 * 24 + lane];
                uint2 u3 = g_xth[(size_t)s3 * 24 + lane];
                float2 a, b;
                a = __half22float2(*reinterpret_cast<__half2*>(&u0.x));
                b = __half22float2(*reinterpret_cast<__half2*>(&u0.y));
                acc.x += w0 * a.x; acc.y += w0 * a.y; acc.z += w0 * b.x; acc.w += w0 * b.y;
                a = __half22float2(*reinterpret_cast<__half2*>(&u1.x));
                b = __half22float2(*reinterpret_cast<__half2*>(&u1.y));
                acc.x += w1 * a.x; acc.y += w1 * a.y; acc.z += w1 * b.x; acc.w += w1 * b.y;
                a = __half22float2(*reinterpret_cast<__half2*>(&u2.x));
                b = __half22float2(*reinterpret_cast<__half2*>(&u2.y));
                acc.x += w2 * a.x; acc.y += w2 * a.y; acc.z += w2 * b.x; acc.w += w2 * b.y;
                a = __half22float2(*reinterpret_cast<__half2*>(&u3.x));
                b = __half22float2(*reinterpret_cast<__half2*>(&u3.y));
                acc.x += w3 * a.x; acc.y += w3 * a.y; acc.z += w3 * b.x; acc.w += w3 * b.y;
            }
        }
        int c2 = cnt - 32;
        for (int j = 0; j < c2; j += 4) {
            int   s0 = __shfl_sync(~0u, sl1.x, j + 0);
            int   s1 = __shfl_sync(~0u, sl1.x, j + 1);
            int   s2 = __shfl_sync(~0u, sl1.x, j + 2);
            int   s3 = __shfl_sync(~0u, sl1.x, j + 3);
            float w0 = __int_as_float(__shfl_sync(~0u, sl1.y, j + 0));
            float w1 = __int_as_float(__shfl_sync(~0u, sl1.y, j + 1));
            float w2 = __int_as_float(__shfl_sync(~0u, sl1.y, j + 2));
            float w3 = __int_as_float(__shfl_sync(~0u, sl1.y, j + 3));
            if (lane < 24) {
                uint2 u0 = g_xth[(size_t)s0 * 24 + lane];
                uint2 u1 = g_xth[(size_t)s1 * 24 + lane];
                uint2 u2 = g_xth[(size_t)s2 * 24 + lane];
                uint2 u3 = g_xth[(size_t)s3 * 24 + lane];
                float2 a, b;
                a = __half22float2(*reinterpret_cast<__half2*>(&u0.x));
                b = __half22float2(*reinterpret_cast<__half2*>(&u0.y));
                acc.x += w0 * a.x; acc.y += w0 * a.y; acc.z += w0 * b.x; acc.w += w0 * b.y;
                a = __half22float2(*reinterpret_cast<__half2*>(&u1.x));
                b = __half22float2(*reinterpret_cast<__half2*>(&u1.y));
                acc.x += w1 * a.x; acc.y += w1 * a.y; acc.z += w1 * b.x; acc.w += w1 * b.y;
                a = __half22float2(*reinterpret_cast<__half2*>(&u2.x));
                b = __half22float2(*reinterpret_cast<__half2*>(&u2.y));
                acc.x += w2 * a.x; acc.y += w2 * a.y; acc.z += w2 * b.x; acc.w += w2 * b.y;
                a = __half22float2(*reinterpret_cast<__half2*>(&u3.x));
                b = __half22float2(*reinterpret_cast<__half2*>(&u3.y));
                acc.x += w3 * a.x; acc.y += w3 * a.y; acc.z += w3 * b.x; acc.w += w3 * b.y;
            }
        }
    } else {
        // Unconditional-correctness fallback (statistically unreachable).
        for (int e = 0; e < NE; ++e) {
            if (__ldg(edst + e) == node) {
                float wt = __ldg(ew + e);
                if (lane < 24) {
                    uint2 u = g_xth[(size_t)__ldg(esrc + e) * 24 + lane];
                    float2 a = __half22float2(*reinterpret_cast<__half2*>(&u.x));
                    float2 b = __half22float2(*reinterpret_cast<__half2*>(&u.y));
                    acc.x += wt * a.x; acc.y += wt * a.y;
                    acc.z += wt * b.x; acc.w += wt * b.y;
                }
            }
        }
    }

    if (lane < 24)
        reinterpret_cast<float4*>(g_agg)[(size_t)node * 24 + lane] = acc;
}

// ---------------------------------------------------------------------------
// k3: epilogue (unchanged from R8). One thread per (node, 4-batch half);
// weights pre-duplicated in smem as float2 {w,w}; LDS.64 + FFMA2 inner loop.
// ---------------------------------------------------------------------------
__global__ void __launch_bounds__(128) k3_out(
        const float* __restrict__ w_gcn, const float* __restrict__ b_gcn,
        const float* __restrict__ w_dense, const float* __restrict__ b_dense,
        float* __restrict__ out) {
    __shared__ float2 s_wg2[NT * NF];   // [t][f] duplicated
    __shared__ float2 s_wd2[NF * NT];   // [f][t] duplicated
    __shared__ float2 s_bg2[NF];
    __shared__ float  s_bd[NT];
    int tid = threadIdx.x;
    for (int i = tid; i < NT * NF; i += 128) {
        float a = w_gcn[i];   s_wg2[i] = make_float2(a, a);
        float b = w_dense[i]; s_wd2[i] = make_float2(b, b);
    }
    if (tid < NF) { float v = b_gcn[tid]; s_bg2[tid] = make_float2(v, v); }
    if (tid < NT) s_bd[tid] = b_dense[tid];
    __syncthreads();

    int gid = blockIdx.x * 128 + tid;     // (n, half): 40000 total
    if (gid >= NN * 2) return;
    int n = gid >> 1, half = gid & 1;     // batches b0 = 4*half .. +3

    unsigned long long A[2][NT], O[2][NT];
    {
        const float4* p = reinterpret_cast<const float4*>(
            g_agg + (size_t)n * NBT + half * 48);
        float a[4][NT];
#pragma unroll
        for (int q = 0; q < 12; ++q) {
            float4 v = p[q];
            int b = q / 3, r = (q % 3) * 4;
            a[b][r + 0] = v.x; a[b][r + 1] = v.y; a[b][r + 2] = v.z; a[b][r + 3] = v.w;
        }
#pragma unroll
        for (int t = 0; t < NT; ++t) {
            A[0][t] = pk2(a[0][t], a[1][t]);
            A[1][t] = pk2(a[2][t], a[3][t]);
            O[0][t] = 0ull;
            O[1][t] = 0ull;
        }
    }

    const unsigned long long* wg2 = reinterpret_cast<const unsigned long long*>(s_wg2);
    const unsigned long long* wd2 = reinterpret_cast<const unsigned long long*>(s_wd2);
    const unsigned long long* bg2 = reinterpret_cast<const unsigned long long*>(s_bg2);

#pragma unroll 4
    for (int f = 0; f < NF; ++f) {
        unsigned long long G0 = bg2[f];
        unsigned long long G1 = G0;
#pragma unroll
        for (int t = 0; t < NT; ++t) {
            unsigned long long w2 = wg2[t * NF + f];
            FFMA2(G0, A[0][t], w2, G0);
            FFMA2(G1, A[1][t], w2, G1);
        }
        float g0l, g0h, g1l, g1h;
        upk2(g0l, g0h, G0); upk2(g1l, g1h, G1);
        G0 = pk2(fmaxf(g0l, 0.f), fmaxf(g0h, 0.f));
        G1 = pk2(fmaxf(g1l, 0.f), fmaxf(g1h, 0.f));
#pragma unroll
        for (int t = 0; t < NT; ++t) {
            unsigned long long w2 = wd2[f * NT + t];
            FFMA2(O[0][t], G0, w2, O[0][t]);
            FFMA2(O[1][t], G1, w2, O[1][t]);
        }
    }

#pragma unroll
    for (int p = 0; p < 2; ++p) {
        float lo[NT], hi[NT];
#pragma unroll
        for (int t = 0; t < NT; ++t) {
            float l, h; upk2(l, h, O[p][t]);
            lo[t] = fmaxf(l + s_bd[t], 0.f);
            hi[t] = fmaxf(h + s_bd[t], 0.f);
        }
        int b_lo = half * 4 + 2 * p;
        float4* q0 = reinterpret_cast<float4*>(out + ((size_t)b_lo * NN + n) * NT);
        float4* q1 = reinterpret_cast<float4*>(out + ((size_t)(b_lo + 1) * NN + n) * NT);
#pragma unroll
        for (int q = 0; q < 3; ++q) {
            q0[q] = make_float4(lo[4*q], lo[4*q+1], lo[4*q+2], lo[4*q+3]);
            q1[q] = make_float4(hi[4*q], hi[4*q+1], hi[4*q+2], hi[4*q+3]);
        }
    }
}

// ---------------------------------------------------------------------------
extern "C" void kernel_launch(void* const* d_in, const int* in_sizes, int n_in,
                              void* d_out, int out_size) {
    const float* x       = (const float*)d_in[0];
    const float* ew      = (const float*)d_in[1];
    const float* w_gcn   = (const float*)d_in[2];
    const float* b_gcn   = (const float*)d_in[3];
    const float* w_dense = (const float*)d_in[4];
    const float* b_dense = (const float*)d_in[5];
    const int*   esrc    = (const int*)d_in[6];
    const int*   edst    = (const int*)d_in[7];
    float* out = (float*)d_out;

    kA<<<TP_BLOCKS + FILL_BLOCKS, 256>>>(x, esrc, edst, ew);
    k2_gather<<<NN / 8, 256>>>(esrc, edst, ew);
    k3_out<<<(NN * 2 + 127) / 128, 128>>>(w_gcn, b_gcn, w_dense, b_dense, out);
}

// round 11
// speedup vs baseline: 1.2288x; 1.2288x over previous
#include <cuda_runtime.h>

#define NB 8       // batch
#define NT 12      // time / feature-in dim
#define NN 20000   // nodes
#define NE 320000  // edges
#define NF 64      // gcn hidden
#define NBT (NB * NT)   // 96 floats per node row
#define CAP 64          // bucket capacity (Poisson(16); P(>64) ~ 1e-20)

#define TP_BLOCKS (NN / 32)        // 625 transpose blocks (32 nodes each)
#define FILL_BLOCKS (NE / 256)     // 1250 fill blocks (exact)

// Scratch (__device__ globals; ~25 MB, L2-resident).
// g_cnt starts zeroed (static init) and is re-zeroed by k2 every call.
__device__ __align__(128) float g_xt [(size_t)NN * NBT];  // [n][b*12+t]
__device__ __align__(128) float g_agg[(size_t)NN * NBT];  // [n][b*12+t]
__device__ __align__(128) int2  g_bkt[(size_t)NN * CAP];  // {src*24, w-as-int}
__device__ int g_cnt[NN];

// ---- f32x2 packed helpers ---------------------------------------------------
__device__ __forceinline__ unsigned long long pk2(float lo, float hi) {
    unsigned long long r;
    asm("mov.b64 %0, {%1, %2};" : "=l"(r) : "f"(lo), "f"(hi));
    return r;
}
__device__ __forceinline__ void upk2(float& lo, float& hi, unsigned long long v) {
    asm("mov.b64 {%0, %1}, %2;" : "=f"(lo), "=f"(hi) : "l"(v));
}
#define FFMA2(d, a, b, c) \
    asm("fma.rn.f32x2 %0, %1, %2, %3;" : "=l"(d) : "l"(a), "l"(b), "l"(c))

// ---------------------------------------------------------------------------
// kA: fused transpose + edge bucketing (R8 fp32 version; bucket stores src*24).
// ---------------------------------------------------------------------------
__global__ void __launch_bounds__(256) kA(
        const float* __restrict__ x,
        const int* __restrict__ esrc, const int* __restrict__ edst,
        const float* __restrict__ ew) {
    __shared__ float s[96 * 33];
    int tid = threadIdx.x;

    if (blockIdx.x < TP_BLOCKS) {
        int n0 = blockIdx.x * 32;
        const float4* x4 = reinterpret_cast<const float4*>(x);
#pragma unroll
        for (int k = 0; k < 3; ++k) {
            int i = tid + 256 * k;
            int bt = i >> 3, q = i & 7;
            float4 v = x4[(size_t)bt * (NN / 4) + (n0 >> 2) + q];
            s[bt * 33 + 4 * q + 0] = v.x;
            s[bt * 33 + 4 * q + 1] = v.y;
            s[bt * 33 + 4 * q + 2] = v.z;
            s[bt * 33 + 4 * q + 3] = v.w;
        }
        __syncthreads();
        float4* dst = reinterpret_cast<float4*>(g_xt) + (size_t)n0 * 24;
#pragma unroll
        for (int k = 0; k < 3; ++k) {
            int o4 = tid + 256 * k;
            int n = o4 / 24, q = o4 % 24, r = 4 * q;
            dst[o4] = make_float4(s[(r + 0) * 33 + n], s[(r + 1) * 33 + n],
                                  s[(r + 2) * 33 + n], s[(r + 3) * 33 + n]);
        }
    } else {
        int e = (blockIdx.x - TP_BLOCKS) * 256 + tid;
        int d = edst[e];
        int pos = atomicAdd(&g_cnt[d], 1);
        if (pos < CAP)
            g_bkt[(size_t)d * CAP + pos] =
                make_int2(esrc[e] * 24, __float_as_int(ew[e]));
    }
}

// ---------------------------------------------------------------------------
// k2: pure gather, one warp per node, 8-edge unroll (8 LDG.128 in flight).
// Bucket slots hold precomputed float4-row index (src*24). Padded slots are
// {0, w=0} -> harmless. Resets g_cnt. fp32 throughout.
// ---------------------------------------------------------------------------
__global__ void __launch_bounds__(256) k2_gather(
        const int* __restrict__ esrc, const int* __restrict__ edst,
        const float* __restrict__ ew) {
    int tid = threadIdx.x;
    int w = tid >> 5, lane = tid & 31;
    int node = blockIdx.x * 8 + w;
    int cnt = g_cnt[node];
    if (lane == 0) g_cnt[node] = 0;

    float4 acc = make_float4(0.f, 0.f, 0.f, 0.f);
    const float4* xt4 = reinterpret_cast<const float4*>(g_xt);

    if (cnt <= CAP) {
        const int2* bp = g_bkt + (size_t)node * CAP;
        int2 sl0 = (lane      < cnt) ? bp[lane]      : make_int2(0, 0);
        int2 sl1 = (lane + 32 < cnt) ? bp[lane + 32] : make_int2(0, 0);

        int c1 = cnt < 32 ? cnt : 32;
        for (int j = 0; j < c1; j += 8) {
            int   sx[8];
            float wv[8];
#pragma unroll
            for (int k = 0; k < 8; ++k) {
                sx[k] = __shfl_sync(~0u, sl0.x, j + k);
                wv[k] = __int_as_float(__shfl_sync(~0u, sl0.y, j + k));
            }
            if (lane < 24) {
                float4 v[8];
#pragma unroll
                for (int k = 0; k < 8; ++k) v[k] = xt4[(size_t)sx[k] + lane];
#pragma unroll
                for (int k = 0; k < 8; ++k) {
                    acc.x += wv[k] * v[k].x;
                    acc.y += wv[k] * v[k].y;
                    acc.z += wv[k] * v[k].z;
                    acc.w += wv[k] * v[k].w;
                }
            }
        }
        int c2 = cnt - 32;
        for (int j = 0; j < c2; j += 8) {
            int   sx[8];
            float wv[8];
#pragma unroll
            for (int k = 0; k < 8; ++k) {
                sx[k] = __shfl_sync(~0u, sl1.x, j + k);
                wv[k] = __int_as_float(__shfl_sync(~0u, sl1.y, j + k));
            }
            if (lane < 24) {
                float4 v[8];
#pragma unroll
                for (int k = 0; k < 8; ++k) v[k] = xt4[(size_t)sx[k] + lane];
#pragma unroll
                for (int k = 0; k < 8; ++k) {
                    acc.x += wv[k] * v[k].x;
                    acc.y += wv[k] * v[k].y;
                    acc.z += wv[k] * v[k].z;
                    acc.w += wv[k] * v[k].w;
                }
            }
        }
    } else {
        // Unconditional-correctness fallback (statistically unreachable).
        for (int e = 0; e < NE; ++e) {
            if (__ldg(edst + e) == node) {
                float wt = __ldg(ew + e);
                if (lane < 24) {
                    float4 v = xt4[(size_t)__ldg(esrc + e) * 24 + lane];
                    acc.x += wt * v.x; acc.y += wt * v.y;
                    acc.z += wt * v.z; acc.w += wt * v.w;
                }
            }
        }
    }

    if (lane < 24)
        reinterpret_cast<float4*>(g_agg)[(size_t)node * 24 + lane] = acc;
}

// ---------------------------------------------------------------------------
// k3: epilogue (unchanged from R8). One thread per (node, 4-batch half);
// weights pre-duplicated in smem as float2 {w,w}; LDS.64 + FFMA2 inner loop.
// ---------------------------------------------------------------------------
__global__ void __launch_bounds__(128) k3_out(
        const float* __restrict__ w_gcn, const float* __restrict__ b_gcn,
        const float* __restrict__ w_dense, const float* __restrict__ b_dense,
        float* __restrict__ out) {
    __shared__ float2 s_wg2[NT * NF];   // [t][f] duplicated
    __shared__ float2 s_wd2[NF * NT];   // [f][t] duplicated
    __shared__ float2 s_bg2[NF];
    __shared__ float  s_bd[NT];
    int tid = threadIdx.x;
    for (int i = tid; i < NT * NF; i += 128) {
        float a = w_gcn[i];   s_wg2[i] = make_float2(a, a);
        float b = w_dense[i]; s_wd2[i] = make_float2(b, b);
    }
    if (tid < NF) { float v = b_gcn[tid]; s_bg2[tid] = make_float2(v, v); }
    if (tid < NT) s_bd[tid] = b_dense[tid];
    __syncthreads();

    int gid = blockIdx.x * 128 + tid;     // (n, half): 40000 total
    if (gid >= NN * 2) return;
    int n = gid >> 1, half = gid & 1;     // batches b0 = 4*half .. +3

    unsigned long long A[2][NT], O[2][NT];
    {
        const float4* p = reinterpret_cast<const float4*>(
            g_agg + (size_t)n * NBT + half * 48);
        float a[4][NT];
#pragma unroll
        for (int q = 0; q < 12; ++q) {
            float4 v = p[q];
            int b = q / 3, r = (q % 3) * 4;
            a[b][r + 0] = v.x; a[b][r + 1] = v.y; a[b][r + 2] = v.z; a[b][r + 3] = v.w;
        }
#pragma unroll
        for (int t = 0; t < NT; ++t) {
            A[0][t] = pk2(a[0][t], a[1][t]);
            A[1][t] = pk2(a[2][t], a[3][t]);
            O[0][t] = 0ull;
            O[1][t] = 0ull;
        }
    }

    const unsigned long long* wg2 = reinterpret_cast<const unsigned long long*>(s_wg2);
    const unsigned long long* wd2 = reinterpret_cast<const unsigned long long*>(s_wd2);
    const unsigned long long* bg2 = reinterpret_cast<const unsigned long long*>(s_bg2);

#pragma unroll 4
    for (int f = 0; f < NF; ++f) {
        unsigned long long G0 = bg2[f];
        unsigned long long G1 = G0;
#pragma unroll
        for (int t = 0; t < NT; ++t) {
            unsigned long long w2 = wg2[t * NF + f];
            FFMA2(G0, A[0][t], w2, G0);
            FFMA2(G1, A[1][t], w2, G1);
        }
        float g0l, g0h, g1l, g1h;
        upk2(g0l, g0h, G0); upk2(g1l, g1h, G1);
        G0 = pk2(fmaxf(g0l, 0.f), fmaxf(g0h, 0.f));
        G1 = pk2(fmaxf(g1l, 0.f), fmaxf(g1h, 0.f));
#pragma unroll
        for (int t = 0; t < NT; ++t) {
            unsigned long long w2 = wd2[f * NT + t];
            FFMA2(O[0][t], G0, w2, O[0][t]);
            FFMA2(O[1][t], G1, w2, O[1][t]);
        }
    }

#pragma unroll
    for (int p = 0; p < 2; ++p) {
        float lo[NT], hi[NT];
#pragma unroll
        for (int t = 0; t < NT; ++t) {
            float l, h; upk2(l, h, O[p][t]);
            lo[t] = fmaxf(l + s_bd[t], 0.f);
            hi[t] = fmaxf(h + s_bd[t], 0.f);
        }
        int b_lo = half * 4 + 2 * p;
        float4* q0 = reinterpret_cast<float4*>(out + ((size_t)b_lo * NN + n) * NT);
        float4* q1 = reinterpret_cast<float4*>(out + ((size_t)(b_lo + 1) * NN + n) * NT);
#pragma unroll
        for (int q = 0; q < 3; ++q) {
            q0[q] = make_float4(lo[4*q], lo[4*q+1], lo[4*q+2], lo[4*q+3]);
            q1[q] = make_float4(hi[4*q], hi[4*q+1], hi[4*q+2], hi[4*q+3]);
        }
    }
}

// ---------------------------------------------------------------------------
extern "C" void kernel_launch(void* const* d_in, const int* in_sizes, int n_in,
                              void* d_out, int out_size) {
    const float* x       = (const float*)d_in[0];
    const float* ew      = (const float*)d_in[1];
    const float* w_gcn   = (const float*)d_in[2];
    const float* b_gcn   = (const float*)d_in[3];
    const float* w_dense = (const float*)d_in[4];
    const float* b_dense = (const float*)d_in[5];
    const int*   esrc    = (const int*)d_in[6];
    const int*   edst    = (const int*)d_in[7];
    float* out = (float*)d_out;

    kA<<<TP_BLOCKS + FILL_BLOCKS, 256>>>(x, esrc, edst, ew);
    k2_gather<<<NN / 8, 256>>>(esrc, edst, ew);
    k3_out<<<(NN * 2 + 127) / 128, 128>>>(w_gcn, b_gcn, w_dense, b_dense, out);
}

// round 12
// speedup vs baseline: 1.2595x; 1.0250x over previous
#include <cuda_runtime.h>

#define NB 8       // batch
#define NT 12      // time / feature-in dim
#define NN 20000   // nodes
#define NE 320000  // edges
#define NF 64      // gcn hidden
#define NBT (NB * NT)   // 96 floats per node row
#define CAP 64          // bucket capacity (Poisson(16); P(>64) ~ 1e-20)

#define TP_BLOCKS (NN / 32)        // 625 transpose blocks (32 nodes each)
#define FILL_BLOCKS (NE / 256)     // 1250 fill blocks (exact)

// Scratch (__device__ globals; ~25 MB, L2-resident).
// g_cnt starts zeroed (static init) and is re-zeroed by k2 every call.
__device__ __align__(128) float g_xt [(size_t)NN * NBT];  // [n][b*12+t]
__device__ __align__(128) float g_agg[(size_t)NN * NBT];  // [n][b*12+t]
__device__ __align__(128) int2  g_bkt[(size_t)NN * CAP];  // {src*24, w-as-int}
__device__ int g_cnt[NN];

// ---- f32x2 packed helpers ---------------------------------------------------
__device__ __forceinline__ unsigned long long pk2(float lo, float hi) {
    unsigned long long r;
    asm("mov.b64 %0, {%1, %2};" : "=l"(r) : "f"(lo), "f"(hi));
    return r;
}
__device__ __forceinline__ void upk2(float& lo, float& hi, unsigned long long v) {
    asm("mov.b64 {%0, %1}, %2;" : "=f"(lo), "=f"(hi) : "l"(v));
}
#define FFMA2(d, a, b, c) \
    asm("fma.rn.f32x2 %0, %1, %2, %3;" : "=l"(d) : "l"(a), "l"(b), "l"(c))

// ---------------------------------------------------------------------------
// kA: fused transpose + edge bucketing (R8 fp32 version; bucket stores src*24).
// ---------------------------------------------------------------------------
__global__ void __launch_bounds__(256) kA(
        const float* __restrict__ x,
        const int* __restrict__ esrc, const int* __restrict__ edst,
        const float* __restrict__ ew) {
    __shared__ float s[96 * 33];
    int tid = threadIdx.x;

    if (blockIdx.x < TP_BLOCKS) {
        int n0 = blockIdx.x * 32;
        const float4* x4 = reinterpret_cast<const float4*>(x);
#pragma unroll
        for (int k = 0; k < 3; ++k) {
            int i = tid + 256 * k;
            int bt = i >> 3, q = i & 7;
            float4 v = x4[(size_t)bt * (NN / 4) + (n0 >> 2) + q];
            s[bt * 33 + 4 * q + 0] = v.x;
            s[bt * 33 + 4 * q + 1] = v.y;
            s[bt * 33 + 4 * q + 2] = v.z;
            s[bt * 33 + 4 * q + 3] = v.w;
        }
        __syncthreads();
        float4* dst = reinterpret_cast<float4*>(g_xt) + (size_t)n0 * 24;
#pragma unroll
        for (int k = 0; k < 3; ++k) {
            int o4 = tid + 256 * k;
            int n = o4 / 24, q = o4 % 24, r = 4 * q;
            dst[o4] = make_float4(s[(r + 0) * 33 + n], s[(r + 1) * 33 + n],
                                  s[(r + 2) * 33 + n], s[(r + 3) * 33 + n]);
        }
    } else {
        int e = (blockIdx.x - TP_BLOCKS) * 256 + tid;
        int d = edst[e];
        int pos = atomicAdd(&g_cnt[d], 1);
        if (pos < CAP)
            g_bkt[(size_t)d * CAP + pos] =
                make_int2(esrc[e] * 24, __float_as_int(ew[e]));
    }
}

// ---------------------------------------------------------------------------
// k2: pure gather, one warp per node, 8-edge unroll (8 LDG.128 in flight).
// Bucket slots hold precomputed float4-row index (src*24). Padded slots are
// {0, w=0} -> harmless. Resets g_cnt. fp32 throughout.
// ---------------------------------------------------------------------------
__global__ void __launch_bounds__(256) k2_gather(
        const int* __restrict__ esrc, const int* __restrict__ edst,
        const float* __restrict__ ew) {
    int tid = threadIdx.x;
    int w = tid >> 5, lane = tid & 31;
    int node = blockIdx.x * 8 + w;
    int cnt = g_cnt[node];
    if (lane == 0) g_cnt[node] = 0;

    float4 acc = make_float4(0.f, 0.f, 0.f, 0.f);
    const float4* xt4 = reinterpret_cast<const float4*>(g_xt);

    if (cnt <= CAP) {
        const int2* bp = g_bkt + (size_t)node * CAP;
        int2 sl0 = (lane      < cnt) ? bp[lane]      : make_int2(0, 0);
        int2 sl1 = (lane + 32 < cnt) ? bp[lane + 32] : make_int2(0, 0);

        int c1 = cnt < 32 ? cnt : 32;
        for (int j = 0; j < c1; j += 8) {
            int   sx[8];
            float wv[8];
#pragma unroll
            for (int k = 0; k < 8; ++k) {
                sx[k] = __shfl_sync(~0u, sl0.x, j + k);
                wv[k] = __int_as_float(__shfl_sync(~0u, sl0.y, j + k));
            }
            if (lane < 24) {
                float4 v[8];
#pragma unroll
                for (int k = 0; k < 8; ++k) v[k] = xt4[(size_t)sx[k] + lane];
#pragma unroll
                for (int k = 0; k < 8; ++k) {
                    acc.x += wv[k] * v[k].x;
                    acc.y += wv[k] * v[k].y;
                    acc.z += wv[k] * v[k].z;
                    acc.w += wv[k] * v[k].w;
                }
            }
        }
        int c2 = cnt - 32;
        for (int j = 0; j < c2; j += 8) {
            int   sx[8];
            float wv[8];
#pragma unroll
            for (int k = 0; k < 8; ++k) {
                sx[k] = __shfl_sync(~0u, sl1.x, j + k);
                wv[k] = __int_as_float(__shfl_sync(~0u, sl1.y, j + k));
            }
            if (lane < 24) {
                float4 v[8];
#pragma unroll
                for (int k = 0; k < 8; ++k) v[k] = xt4[(size_t)sx[k] + lane];
#pragma unroll
                for (int k = 0; k < 8; ++k) {
                    acc.x += wv[k] * v[k].x;
                    acc.y += wv[k] * v[k].y;
                    acc.z += wv[k] * v[k].z;
                    acc.w += wv[k] * v[k].w;
                }
            }
        }
    } else {
        // Unconditional-correctness fallback (statistically unreachable).
        for (int e = 0; e < NE; ++e) {
            if (__ldg(edst + e) == node) {
                float wt = __ldg(ew + e);
                if (lane < 24) {
                    float4 v = xt4[(size_t)__ldg(esrc + e) * 24 + lane];
                    acc.x += wt * v.x; acc.y += wt * v.y;
                    acc.z += wt * v.z; acc.w += wt * v.w;
                }
            }
        }
    }

    if (lane < 24)
        reinterpret_cast<float4*>(g_agg)[(size_t)node * 24 + lane] = acc;
}

// ---------------------------------------------------------------------------
// k3: epilogue (unchanged from R8). One thread per (node, 4-batch half);
// weights pre-duplicated in smem as float2 {w,w}; LDS.64 + FFMA2 inner loop.
// ---------------------------------------------------------------------------
__global__ void __launch_bounds__(128) k3_out(
        const float* __restrict__ w_gcn, const float* __restrict__ b_gcn,
        const float* __restrict__ w_dense, const float* __restrict__ b_dense,
        float* __restrict__ out) {
    __shared__ float2 s_wg2[NT * NF];   // [t][f] duplicated
    __shared__ float2 s_wd2[NF * NT];   // [f][t] duplicated
    __shared__ float2 s_bg2[NF];
    __shared__ float  s_bd[NT];
    int tid = threadIdx.x;
    for (int i = tid; i < NT * NF; i += 128) {
        float a = w_gcn[i];   s_wg2[i] = make_float2(a, a);
        float b = w_dense[i]; s_wd2[i] = make_float2(b, b);
    }
    if (tid < NF) { float v = b_gcn[tid]; s_bg2[tid] = make_float2(v, v); }
    if (tid < NT) s_bd[tid] = b_dense[tid];
    __syncthreads();

    int gid = blockIdx.x * 128 + tid;     // (n, half): 40000 total
    if (gid >= NN * 2) return;
    int n = gid >> 1, half = gid & 1;     // batches b0 = 4*half .. +3

    unsigned long long A[2][NT], O[2][NT];
    {
        const float4* p = reinterpret_cast<const float4*>(
            g_agg + (size_t)n * NBT + half * 48);
        float a[4][NT];
#pragma unroll
        for (int q = 0; q < 12; ++q) {
            float4 v = p[q];
            int b = q / 3, r = (q % 3) * 4;
            a[b][r + 0] = v.x; a[b][r + 1] = v.y; a[b][r + 2] = v.z; a[b][r + 3] = v.w;
        }
#pragma unroll
        for (int t = 0; t < NT; ++t) {
            A[0][t] = pk2(a[0][t], a[1][t]);
            A[1][t] = pk2(a[2][t], a[3][t]);
            O[0][t] = 0ull;
            O[1][t] = 0ull;
        }
    }

    const unsigned long long* wg2 = reinterpret_cast<const unsigned long long*>(s_wg2);
    const unsigned long long* wd2 = reinterpret_cast<const unsigned long long*>(s_wd2);
    const unsigned long long* bg2 = reinterpret_cast<const unsigned long long*>(s_bg2);

#pragma unroll 4
    for (int f = 0; f < NF; ++f) {
        unsigned long long G0 = bg2[f];
        unsigned long long G1 = G0;
#pragma unroll
        for (int t = 0; t < NT; ++t) {
            unsigned long long w2 = wg2[t * NF + f];
            FFMA2(G0, A[0][t], w2, G0);
            FFMA2(G1, A[1][t], w2, G1);
        }
        float g0l, g0h, g1l, g1h;
        upk2(g0l, g0h, G0); upk2(g1l, g1h, G1);
        G0 = pk2(fmaxf(g0l, 0.f), fmaxf(g0h, 0.f));
        G1 = pk2(fmaxf(g1l, 0.f), fmaxf(g1h, 0.f));
#pragma unroll
        for (int t = 0; t < NT; ++t) {
            unsigned long long w2 = wd2[f * NT + t];
            FFMA2(O[0][t], G0, w2, O[0][t]);
            FFMA2(O[1][t], G1, w2, O[1][t]);
        }
    }

#pragma unroll
    for (int p = 0; p < 2; ++p) {
        float lo[NT], hi[NT];
#pragma unroll
        for (int t = 0; t < NT; ++t) {
            float l, h; upk2(l, h, O[p][t]);
            lo[t] = fmaxf(l + s_bd[t], 0.f);
            hi[t] = fmaxf(h + s_bd[t], 0.f);
        }
        int b_lo = half * 4 + 2 * p;
        float4* q0 = reinterpret_cast<float4*>(out + ((size_t)b_lo * NN + n) * NT);
        float4* q1 = reinterpret_cast<float4*>(out + ((size_t)(b_lo + 1) * NN + n) * NT);
#pragma unroll
        for (int q = 0; q < 3; ++q) {
            q0[q] = make_float4(lo[4*q], lo[4*q+1], lo[4*q+2], lo[4*q+3]);
            q1[q] = make_float4(hi[4*q], hi[4*q+1], hi[4*q+2], hi[4*q+3]);
        }
    }
}

// ---------------------------------------------------------------------------
extern "C" void kernel_launch(void* const* d_in, const int* in_sizes, int n_in,
                              void* d_out, int out_size) {
    const float* x       = (const float*)d_in[0];
    const float* ew      = (const float*)d_in[1];
    const float* w_gcn   = (const float*)d_in[2];
    const float* b_gcn   = (const float*)d_in[3];
    const float* w_dense = (const float*)d_in[4];
    const float* b_dense = (const float*)d_in[5];
    const int*   esrc    = (const int*)d_in[6];
    const int*   edst    = (const int*)d_in[7];
    float* out = (float*)d_out;

    kA<<<TP_BLOCKS + FILL_BLOCKS, 256>>>(x, esrc, edst, ew);
    k2_gather<<<NN / 8, 256>>>(esrc, edst, ew);
    k3_out<<<(NN * 2 + 127) / 128, 128>>>(w_gcn, b_gcn, w_dense, b_dense, out);
}

// round 13
// speedup vs baseline: 1.6929x; 1.3441x over previous
#include <cuda_runtime.h>

#define NB 8       // batch
#define NT 12      // time / feature-in dim
#define NN 20000   // nodes
#define NE 320000  // edges
#define NF 64      // gcn hidden
#define NBT (NB * NT)   // 96 floats per node row
#define CAP 64          // bucket capacity (Poisson(16); P(>64) ~ 1e-20)

// Scratch (__device__ globals; ~25 MB, L2-resident).
// g_cnt starts zeroed (static init) and is re-zeroed by k2 every call.
__device__ __align__(128) float g_xt [(size_t)NN * NBT];  // [n][b*12+t]
__device__ __align__(128) float g_agg[(size_t)NN * NBT];  // [n][b*12+t]
__device__ __align__(128) int2  g_bkt[(size_t)NN * CAP];  // {src*24, w-as-int}
__device__ int g_cnt[NN];

// ---- f32x2 packed helpers ---------------------------------------------------
__device__ __forceinline__ unsigned long long pk2(float lo, float hi) {
    unsigned long long r;
    asm("mov.b64 %0, {%1, %2};" : "=l"(r) : "f"(lo), "f"(hi));
    return r;
}
__device__ __forceinline__ void upk2(float& lo, float& hi, unsigned long long v) {
    asm("mov.b64 {%0, %1}, %2;" : "=f"(lo), "=f"(hi) : "l"(v));
}
#define FFMA2(d, a, b, c) \
    asm("fma.rn.f32x2 %0, %1, %2, %3;" : "=l"(d) : "l"(a), "l"(b), "l"(c))

// ---------------------------------------------------------------------------
// kT: transpose x[B,T,N] -> g_xt[N][B*T], 32-node tiles, float4 both ways.
// ---------------------------------------------------------------------------
__global__ void __launch_bounds__(256) kT(const float* __restrict__ x) {
    __shared__ float s[96 * 33];
    int tid = threadIdx.x;
    int n0 = blockIdx.x * 32;
    const float4* x4 = reinterpret_cast<const float4*>(x);
#pragma unroll
    for (int k = 0; k < 3; ++k) {
        int i = tid + 256 * k;
        int bt = i >> 3, q = i & 7;
        float4 v = x4[(size_t)bt * (NN / 4) + (n0 >> 2) + q];
        s[bt * 33 + 4 * q + 0] = v.x;
        s[bt * 33 + 4 * q + 1] = v.y;
        s[bt * 33 + 4 * q + 2] = v.z;
        s[bt * 33 + 4 * q + 3] = v.w;
    }
    __syncthreads();
    float4* dst = reinterpret_cast<float4*>(g_xt) + (size_t)n0 * 24;
#pragma unroll
    for (int k = 0; k < 3; ++k) {
        int o4 = tid + 256 * k;
        int n = o4 / 24, q = o4 % 24, r = 4 * q;
        dst[o4] = make_float4(s[(r + 0) * 33 + n], s[(r + 1) * 33 + n],
                              s[(r + 2) * 33 + n], s[(r + 3) * 33 + n]);
    }
}

// ---------------------------------------------------------------------------
// kF: bucket edges by destination (slot stores src*24 and weight bits).
// ---------------------------------------------------------------------------
__global__ void __launch_bounds__(256) kF(
        const int* __restrict__ esrc, const int* __restrict__ edst,
        const float* __restrict__ ew) {
    int e = blockIdx.x * 256 + threadIdx.x;   // grid exact: NE/256 blocks
    int d = edst[e];
    int pos = atomicAdd(&g_cnt[d], 1);
    if (pos < CAP)
        g_bkt[(size_t)d * CAP + pos] = make_int2(esrc[e] * 24, __float_as_int(ew[e]));
}

// ---------------------------------------------------------------------------
// k2: gather, one warp per node. Block stages all 8 nodes' bucket slots into
// smem with ONE coalesced 4KB burst (256 int4), then the inner loop reads
// slots via broadcast LDS (no shfl, no per-warp serial L2 dependency).
// 8 LDG.128 in flight per iteration. Resets g_cnt.
// ---------------------------------------------------------------------------
__global__ void __launch_bounds__(256) k2_gather(
        const int* __restrict__ esrc, const int* __restrict__ edst,
        const float* __restrict__ ew) {
    __shared__ int2 s_slot[8][CAP];   // 4 KB
    __shared__ int  s_cnt[8];

    int tid = threadIdx.x;
    int w = tid >> 5, lane = tid & 31;
    int node0 = blockIdx.x * 8;

    // Stage: 8 nodes x 64 slots = 256 int4, one per thread, fully coalesced.
    reinterpret_cast<int4*>(&s_slot[0][0])[tid] =
        reinterpret_cast<const int4*>(g_bkt + (size_t)node0 * CAP)[tid];
    if (tid < 8) {
        int nd = node0 + tid;
        s_cnt[tid] = g_cnt[nd];
        g_cnt[nd] = 0;                // leave zeroed for next call
    }
    __syncthreads();

    int node = node0 + w;
    int cnt = s_cnt[w];

    float4 acc = make_float4(0.f, 0.f, 0.f, 0.f);
    const float4* xt4 = reinterpret_cast<const float4*>(g_xt);

    if (cnt <= CAP) {
        for (int j = 0; j < cnt; j += 8) {
            int   sx[8];
            float wv[8];
#pragma unroll
            for (int k = 0; k < 8; ++k) {
                int idx = j + k;
                int2 sv = (idx < cnt) ? s_slot[w][idx] : make_int2(0, 0);
                sx[k] = sv.x;
                wv[k] = __int_as_float(sv.y);
            }
            if (lane < 24) {
                float4 v[8];
#pragma unroll
                for (int k = 0; k < 8; ++k) v[k] = __ldg(&xt4[(size_t)sx[k] + lane]);
#pragma unroll
                for (int k = 0; k < 8; ++k) {
                    acc.x += wv[k] * v[k].x;
                    acc.y += wv[k] * v[k].y;
                    acc.z += wv[k] * v[k].z;
                    acc.w += wv[k] * v[k].w;
                }
            }
        }
    } else {
        // Unconditional-correctness fallback (statistically unreachable).
        for (int e = 0; e < NE; ++e) {
            if (__ldg(edst + e) == node) {
                float wt = __ldg(ew + e);
                if (lane < 24) {
                    float4 v = __ldg(&xt4[(size_t)__ldg(esrc + e) * 24 + lane]);
                    acc.x += wt * v.x; acc.y += wt * v.y;
                    acc.z += wt * v.z; acc.w += wt * v.w;
                }
            }
        }
    }

    if (lane < 24)
        reinterpret_cast<float4*>(g_agg)[(size_t)node * 24 + lane] = acc;
}

// ---------------------------------------------------------------------------
// k3: epilogue (unchanged). One thread per (node, 4-batch half); weights
// pre-duplicated in smem as float2 {w,w}; LDS.64 + FFMA2 inner loop.
// ---------------------------------------------------------------------------
__global__ void __launch_bounds__(128) k3_out(
        const float* __restrict__ w_gcn, const float* __restrict__ b_gcn,
        const float* __restrict__ w_dense, const float* __restrict__ b_dense,
        float* __restrict__ out) {
    __shared__ float2 s_wg2[NT * NF];   // [t][f] duplicated
    __shared__ float2 s_wd2[NF * NT];   // [f][t] duplicated
    __shared__ float2 s_bg2[NF];
    __shared__ float  s_bd[NT];
    int tid = threadIdx.x;
    for (int i = tid; i < NT * NF; i += 128) {
        float a = w_gcn[i];   s_wg2[i] = make_float2(a, a);
        float b = w_dense[i]; s_wd2[i] = make_float2(b, b);
    }
    if (tid < NF) { float v = b_gcn[tid]; s_bg2[tid] = make_float2(v, v); }
    if (tid < NT) s_bd[tid] = b_dense[tid];
    __syncthreads();

    int gid = blockIdx.x * 128 + tid;     // (n, half): 40000 total
    if (gid >= NN * 2) return;
    int n = gid >> 1, half = gid & 1;     // batches b0 = 4*half .. +3

    unsigned long long A[2][NT], O[2][NT];
    {
        const float4* p = reinterpret_cast<const float4*>(
            g_agg + (size_t)n * NBT + half * 48);
        float a[4][NT];
#pragma unroll
        for (int q = 0; q < 12; ++q) {
            float4 v = p[q];
            int b = q / 3, r = (q % 3) * 4;
            a[b][r + 0] = v.x; a[b][r + 1] = v.y; a[b][r + 2] = v.z; a[b][r + 3] = v.w;
        }
#pragma unroll
        for (int t = 0; t < NT; ++t) {
            A[0][t] = pk2(a[0][t], a[1][t]);
            A[1][t] = pk2(a[2][t], a[3][t]);
            O[0][t] = 0ull;
            O[1][t] = 0ull;
        }
    }

    const unsigned long long* wg2 = reinterpret_cast<const unsigned long long*>(s_wg2);
    const unsigned long long* wd2 = reinterpret_cast<const unsigned long long*>(s_wd2);
    const unsigned long long* bg2 = reinterpret_cast<const unsigned long long*>(s_bg2);

#pragma unroll 4
    for (int f = 0; f < NF; ++f) {
        unsigned long long G0 = bg2[f];
        unsigned long long G1 = G0;
#pragma unroll
        for (int t = 0; t < NT; ++t) {
            unsigned long long w2 = wg2[t * NF + f];
            FFMA2(G0, A[0][t], w2, G0);
            FFMA2(G1, A[1][t], w2, G1);
        }
        float g0l, g0h, g1l, g1h;
        upk2(g0l, g0h, G0); upk2(g1l, g1h, G1);
        G0 = pk2(fmaxf(g0l, 0.f), fmaxf(g0h, 0.f));
        G1 = pk2(fmaxf(g1l, 0.f), fmaxf(g1h, 0.f));
#pragma unroll
        for (int t = 0; t < NT; ++t) {
            unsigned long long w2 = wd2[f * NT + t];
            FFMA2(O[0][t], G0, w2, O[0][t]);
            FFMA2(O[1][t], G1, w2, O[1][t]);
        }
    }

#pragma unroll
    for (int p = 0; p < 2; ++p) {
        float lo[NT], hi[NT];
#pragma unroll
        for (int t = 0; t < NT; ++t) {
            float l, h; upk2(l, h, O[p][t]);
            lo[t] = fmaxf(l + s_bd[t], 0.f);
            hi[t] = fmaxf(h + s_bd[t], 0.f);
        }
        int b_lo = half * 4 + 2 * p;
        float4* q0 = reinterpret_cast<float4*>(out + ((size_t)b_lo * NN + n) * NT);
        float4* q1 = reinterpret_cast<float4*>(out + ((size_t)(b_lo + 1) * NN + n) * NT);
#pragma unroll
        for (int q = 0; q < 3; ++q) {
            q0[q] = make_float4(lo[4*q], lo[4*q+1], lo[4*q+2], lo[4*q+3]);
            q1[q] = make_float4(hi[4*q], hi[4*q+1], hi[4*q+2], hi[4*q+3]);
        }
    }
}

// ---------------------------------------------------------------------------
extern "C" void kernel_launch(void* const* d_in, const int* in_sizes, int n_in,
                              void* d_out, int out_size) {
    const float* x       = (const float*)d_in[0];
    const float* ew      = (const float*)d_in[1];
    const float* w_gcn   = (const float*)d_in[2];
    const float* b_gcn   = (const float*)d_in[3];
    const float* w_dense = (const float*)d_in[4];
    const float* b_dense = (const float*)d_in[5];
    const int*   esrc    = (const int*)d_in[6];
    const int*   edst    = (const int*)d_in[7];
    float* out = (float*)d_out;

    kT<<<NN / 32, 256>>>(x);
    kF<<<NE / 256, 256>>>(esrc, edst, ew);
    k2_gather<<<NN / 8, 256>>>(esrc, edst, ew);
    k3_out<<<(NN * 2 + 127) / 128, 128>>>(w_gcn, b_gcn, w_dense, b_dense, out);
}